// round 4
// baseline (speedup 1.0000x reference)
#include <cuda_runtime.h>

#define B_    512
#define HW_   128
#define C1_   32
#define C2_   64

// Intermediate h: [512, 32, 64, 64] fp32 = 256 MB (static __device__, no alloc)
__device__ float g_h[(size_t)B_ * C1_ * 64 * 64];

// ---------------------------------------------------------------------------
// Kernel 1: Conv(3->32, k3, s1, p1) + bias + BN + ReLU + MaxPool2  (at FFMA wall)
// ---------------------------------------------------------------------------
__global__ void __launch_bounds__(256) conv1_fused(
    const float* __restrict__ crops,
    const float* __restrict__ w1, const float* __restrict__ b1,
    const float* __restrict__ g1, const float* __restrict__ be1,
    const float* __restrict__ m1, const float* __restrict__ v1)
{
    __shared__ float s_in[3][34][36];
    __shared__ __align__(16) float s_w[C1_ * 36];  // [oc][ci][ky][4] pre-scaled
    __shared__ float s_scale[C1_], s_bias[C1_];

    const int b   = blockIdx.z;
    const int cx0 = blockIdx.x * 32;
    const int cy0 = blockIdx.y * 32;
    const int t   = threadIdx.x;

    if (t < C1_) {
        float inv = g1[t] * rsqrtf(v1[t] + 1e-5f);
        s_scale[t] = inv;
        s_bias[t]  = be1[t] + (b1[t] - m1[t]) * inv;
    }

    const float* cb = crops + (size_t)b * 3 * HW_ * HW_;
    for (int i = t; i < 3 * 34 * 34; i += 256) {
        int ci = i / (34 * 34);
        int rem = i % (34 * 34);
        int r = rem / 34, c = rem % 34;
        int gr = cy0 - 1 + r, gc = cx0 - 1 + c;
        float v = 0.f;
        if (gr >= 0 && gr < HW_ && gc >= 0 && gc < HW_)
            v = cb[ci * HW_ * HW_ + gr * HW_ + gc];
        s_in[ci][r][c] = v;
    }
    __syncthreads();

    for (int i = t; i < C1_ * 27; i += 256) {
        int oc = i / 27, k = i % 27;
        int ci = k / 9, ky = (k % 9) / 3, kx = k % 3;
        s_w[oc * 36 + ci * 12 + ky * 4 + kx] = w1[i] * s_scale[oc];
    }
    __syncthreads();

    const int px = t & 15, py = t >> 4;

    float p[3][4][4];
#pragma unroll
    for (int ci = 0; ci < 3; ci++)
#pragma unroll
        for (int r = 0; r < 4; r++) {
            float2 a  = *(const float2*)&s_in[ci][2 * py + r][2 * px];
            float2 c2 = *(const float2*)&s_in[ci][2 * py + r][2 * px + 2];
            p[ci][r][0] = a.x;  p[ci][r][1] = a.y;
            p[ci][r][2] = c2.x; p[ci][r][3] = c2.y;
        }

    float* hb = g_h + (size_t)b * C1_ * 64 * 64;
    const int oy = blockIdx.y * 16 + py;
    const int ox = blockIdx.x * 16 + px;

    for (int oc = 0; oc < C1_; oc++) {
        float a00 = 0.f, a01 = 0.f, a10 = 0.f, a11 = 0.f;
        const float4* w4 = (const float4*)&s_w[oc * 36];
#pragma unroll
        for (int ci = 0; ci < 3; ci++)
#pragma unroll
            for (int ky = 0; ky < 3; ky++) {
                float4 w = w4[ci * 3 + ky];
                a00 = fmaf(p[ci][ky    ][0], w.x, a00);
                a01 = fmaf(p[ci][ky    ][1], w.x, a01);
                a10 = fmaf(p[ci][ky + 1][0], w.x, a10);
                a11 = fmaf(p[ci][ky + 1][1], w.x, a11);
                a00 = fmaf(p[ci][ky    ][1], w.y, a00);
                a01 = fmaf(p[ci][ky    ][2], w.y, a01);
                a10 = fmaf(p[ci][ky + 1][1], w.y, a10);
                a11 = fmaf(p[ci][ky + 1][2], w.y, a11);
                a00 = fmaf(p[ci][ky    ][2], w.z, a00);
                a01 = fmaf(p[ci][ky    ][3], w.z, a01);
                a10 = fmaf(p[ci][ky + 1][2], w.z, a10);
                a11 = fmaf(p[ci][ky + 1][3], w.z, a11);
            }
        float mv = fmaxf(fmaxf(a00, a01), fmaxf(a10, a11)) + s_bias[oc];
        hb[oc * 64 * 64 + oy * 64 + ox] = fmaxf(mv, 0.f);
    }
}

// ---------------------------------------------------------------------------
// Kernel 2: Conv(32->64, k3, s2, p1) + BN + Sigmoid + MaxPool2
// Double-buffered smem (dynamic, ~63 KB): overlap next chunk's LDG/STS with
// current chunk's FMA; one __syncthreads per chunk.
// Layout (floats):
//   s_in : [2][4][33][36]              9504
//   s_w  : [2][64][4][3][4] prescaled  6144   (offset 9504)
//   s_scale[64] @15648, s_bias[64] @15712
// ---------------------------------------------------------------------------
#define IN_OFF(p,cil,r)   ((((p)*4 + (cil))*33 + (r))*36)
#define W_OFF(p,oc,cil)   (9504 + (p)*3072 + (oc)*48 + (cil)*12)
#define SC_OFF            15648
#define BI_OFF            15712
#define CONV2_SMEM_BYTES  (15776 * 4)

__global__ void __launch_bounds__(256) conv2_fused(
    const float* __restrict__ w2, const float* __restrict__ b2,
    const float* __restrict__ g2, const float* __restrict__ be2,
    const float* __restrict__ m2, const float* __restrict__ v2,
    float* __restrict__ feat)
{
    extern __shared__ __align__(16) float sm[];

    const int b  = blockIdx.z;
    const int bx = blockIdx.x, by = blockIdx.y;
    const int t  = threadIdx.x;

    if (t < C2_) {
        float inv = g2[t] * rsqrtf(v2[t] + 1e-5f);
        sm[SC_OFF + t] = inv;
        sm[BI_OFF + t] = be2[t] + (b2[t] - m2[t]) * inv;
    }
    __syncthreads();                       // scale ready for weight fill

    const float* hb = g_h + (size_t)b * C1_ * 64 * 64;
    const int r0 = 32 * by - 1;
    const int c0 = 32 * bx - 1;

    // ---- chunk fill (chunk cc -> buffer p); no sync inside ----
    auto fill = [&](int cc, int p) {
        // weights first: their LDGs issue earliest
        for (int i = t; i < C2_ * 36; i += 256) {
            int oc = i / 36, rem = i % 36;
            int cil = rem / 9, k = rem % 9;
            int ky = k / 3, kx = k % 3;
            sm[W_OFF(p, oc, cil) + ky * 4 + kx] =
                w2[oc * (C1_ * 9) + (cc * 4 + cil) * 9 + k] * sm[SC_OFF + oc];
        }
#pragma unroll
        for (int cil = 0; cil < 4; cil++) {
            const float* src = hb + (cc * 4 + cil) * 4096;
            float* dst = &sm[IN_OFF(p, cil, 0)];
            for (int i = t; i < 33 * 33; i += 256) {
                int r = i / 33, c = i % 33;
                int gr = r0 + r, gc = c0 + c;
                float v = 0.f;
                if (gr >= 0 && gr < 64 && gc >= 0 && gc < 64)
                    v = src[gr * 64 + gc];
                dst[r * 36 + c] = v;
            }
        }
    };

    const int pix = t & 63, grp = t >> 6;      // grp 0..3 -> 16 oc each
    const int px = pix & 7, py = pix >> 3;

    float acc[16][2][2];
#pragma unroll
    for (int i = 0; i < 16; i++) {
        acc[i][0][0] = 0.f; acc[i][0][1] = 0.f;
        acc[i][1][0] = 0.f; acc[i][1][1] = 0.f;
    }

    fill(0, 0);
    __syncthreads();

    for (int cc = 0; cc < 8; cc++) {
        const int cur = cc & 1;
        if (cc < 7) fill(cc + 1, cur ^ 1);     // overlap with compute below

#pragma unroll
        for (int cil = 0; cil < 4; cil++) {
            const float* row = &sm[IN_OFF(cur, cil, 4 * py) + 4 * px];
            float p[5][5];
#pragma unroll
            for (int r = 0; r < 5; r++) {
                float4 v4 = *(const float4*)(row + r * 36);
                p[r][0] = v4.x; p[r][1] = v4.y; p[r][2] = v4.z; p[r][3] = v4.w;
                p[r][4] = row[r * 36 + 4];
            }

#pragma unroll
            for (int oc = 0; oc < 16; oc++) {
                const float4* w4 = (const float4*)&sm[W_OFF(cur, grp * 16 + oc, cil)];
#pragma unroll
                for (int ky = 0; ky < 3; ky++) {
                    float4 w = w4[ky];
                    acc[oc][0][0] = fmaf(p[ky    ][0], w.x, acc[oc][0][0]);
                    acc[oc][0][1] = fmaf(p[ky    ][2], w.x, acc[oc][0][1]);
                    acc[oc][1][0] = fmaf(p[ky + 2][0], w.x, acc[oc][1][0]);
                    acc[oc][1][1] = fmaf(p[ky + 2][2], w.x, acc[oc][1][1]);
                    acc[oc][0][0] = fmaf(p[ky    ][1], w.y, acc[oc][0][0]);
                    acc[oc][0][1] = fmaf(p[ky    ][3], w.y, acc[oc][0][1]);
                    acc[oc][1][0] = fmaf(p[ky + 2][1], w.y, acc[oc][1][0]);
                    acc[oc][1][1] = fmaf(p[ky + 2][3], w.y, acc[oc][1][1]);
                    acc[oc][0][0] = fmaf(p[ky    ][2], w.z, acc[oc][0][0]);
                    acc[oc][0][1] = fmaf(p[ky    ][4], w.z, acc[oc][0][1]);
                    acc[oc][1][0] = fmaf(p[ky + 2][2], w.z, acc[oc][1][0]);
                    acc[oc][1][1] = fmaf(p[ky + 2][4], w.z, acc[oc][1][1]);
                }
            }
        }
        __syncthreads();   // next buffer filled; all readers done before overwrite
    }

    // Epilogue: max-pool -> +bias -> sigmoid (conv pre-scaled; gamma>0)
    const int oy = by * 8 + py, ox = bx * 8 + px;
    float* fb = feat + (size_t)b * C2_ * 16 * 16;
#pragma unroll
    for (int oc = 0; oc < 16; oc++) {
        int c = grp * 16 + oc;
        float m = fmaxf(fmaxf(acc[oc][0][0], acc[oc][0][1]),
                        fmaxf(acc[oc][1][0], acc[oc][1][1]));
        float v = m + sm[BI_OFF + c];
        fb[c * 256 + oy * 16 + ox] = 1.f / (1.f + __expf(-v));
    }
}

// ---------------------------------------------------------------------------
// Kernel 3: per-image mean over feat [64,16,16] -> scores + detected
// ---------------------------------------------------------------------------
__global__ void __launch_bounds__(256) score_reduce(
    const float* __restrict__ feat,
    float* __restrict__ scores,
    float* __restrict__ detected)
{
    const int b = blockIdx.x;
    const float4* fb = (const float4*)(feat + (size_t)b * 16384);
    float s = 0.f;
    for (int i = threadIdx.x; i < 4096; i += 256) {
        float4 v = fb[i];
        s += (v.x + v.y) + (v.z + v.w);
    }

    __shared__ float red[8];
#pragma unroll
    for (int o = 16; o > 0; o >>= 1) s += __shfl_down_sync(0xffffffffu, s, o);
    if ((threadIdx.x & 31) == 0) red[threadIdx.x >> 5] = s;
    __syncthreads();
    if (threadIdx.x < 8) {
        s = red[threadIdx.x];
#pragma unroll
        for (int o = 4; o > 0; o >>= 1) s += __shfl_down_sync(0xffu, s, o);
        if (threadIdx.x == 0) {
            float sc = s * (1.f / 16384.f);
            scores[b]   = sc;
            detected[b] = (sc >= 0.55f) ? 1.f : 0.f;
        }
    }
}

// ---------------------------------------------------------------------------
extern "C" void kernel_launch(void* const* d_in, const int* in_sizes, int n_in,
                              void* d_out, int out_size)
{
    const float* crops = (const float*)d_in[0];
    const float* w1  = (const float*)d_in[1];
    const float* b1  = (const float*)d_in[2];
    const float* g1  = (const float*)d_in[3];
    const float* be1 = (const float*)d_in[4];
    const float* m1  = (const float*)d_in[5];
    const float* v1  = (const float*)d_in[6];
    const float* w2  = (const float*)d_in[7];
    const float* b2  = (const float*)d_in[8];
    const float* g2  = (const float*)d_in[9];
    const float* be2 = (const float*)d_in[10];
    const float* m2  = (const float*)d_in[11];
    const float* v2  = (const float*)d_in[12];

    float* out      = (float*)d_out;
    float* feat     = out;                                   // 512*64*16*16
    float* scores   = out + (size_t)B_ * C2_ * 16 * 16;      // +512
    float* detected = scores + B_;                           // +512

    static int smem_set = 0;
    if (!smem_set) {
        cudaFuncSetAttribute(conv2_fused,
                             cudaFuncAttributeMaxDynamicSharedMemorySize,
                             CONV2_SMEM_BYTES);
        smem_set = 1;
    }

    conv1_fused<<<dim3(4, 4, B_), 256>>>(crops, w1, b1, g1, be1, m1, v1);
    conv2_fused<<<dim3(2, 2, B_), 256, CONV2_SMEM_BYTES>>>(w2, b2, g2, be2, m2, v2, feat);
    score_reduce<<<B_, 256>>>(feat, scores, detected);
}

// round 5
// speedup vs baseline: 1.0725x; 1.0725x over previous
#include <cuda_runtime.h>

#define B_    512
#define HW_   128
#define C1_   32
#define C2_   64

// Padded intermediate h: [512][32][66][68], zero border (rows 0,65; cols 0,65..67).
// Valid data at [1..64][1..64]. Static __device__ -> zero-initialized at load;
// border never written, so it stays zero across all replays (deterministic).
#define HP_R   66
#define HP_C   68
#define HP_CH  (HP_R * HP_C)          // 4488
__device__ float g_h[(size_t)B_ * C1_ * HP_CH];   // ~294 MB

// ---------------------------------------------------------------------------
// Kernel 1: Conv(3->32, k3, s1, p1) + BN + ReLU + MaxPool2  (near FFMA wall)
// Grid (4,4,512), 256 thr. Writes padded layout.
// ---------------------------------------------------------------------------
__global__ void __launch_bounds__(256) conv1_fused(
    const float* __restrict__ crops,
    const float* __restrict__ w1, const float* __restrict__ b1,
    const float* __restrict__ g1, const float* __restrict__ be1,
    const float* __restrict__ m1, const float* __restrict__ v1)
{
    __shared__ float s_in[3][34][36];
    __shared__ __align__(16) float s_w[C1_ * 36];  // [oc][ci][ky][4] pre-scaled
    __shared__ float s_scale[C1_], s_bias[C1_];

    const int b   = blockIdx.z;
    const int cx0 = blockIdx.x * 32;
    const int cy0 = blockIdx.y * 32;
    const int t   = threadIdx.x;

    if (t < C1_) {
        float inv = g1[t] * rsqrtf(v1[t] + 1e-5f);
        s_scale[t] = inv;
        s_bias[t]  = be1[t] + (b1[t] - m1[t]) * inv;
    }

    const float* cb = crops + (size_t)b * 3 * HW_ * HW_;
    for (int i = t; i < 3 * 34 * 34; i += 256) {
        int ci = i / (34 * 34);
        int rem = i % (34 * 34);
        int r = rem / 34, c = rem % 34;
        int gr = cy0 - 1 + r, gc = cx0 - 1 + c;
        float v = 0.f;
        if (gr >= 0 && gr < HW_ && gc >= 0 && gc < HW_)
            v = cb[ci * HW_ * HW_ + gr * HW_ + gc];
        s_in[ci][r][c] = v;
    }
    __syncthreads();

    for (int i = t; i < C1_ * 27; i += 256) {
        int oc = i / 27, k = i % 27;
        int ci = k / 9, ky = (k % 9) / 3, kx = k % 3;
        s_w[oc * 36 + ci * 12 + ky * 4 + kx] = w1[i] * s_scale[oc];
    }
    __syncthreads();

    const int px = t & 15, py = t >> 4;

    float p[3][4][4];
#pragma unroll
    for (int ci = 0; ci < 3; ci++)
#pragma unroll
        for (int r = 0; r < 4; r++) {
            float2 a  = *(const float2*)&s_in[ci][2 * py + r][2 * px];
            float2 c2 = *(const float2*)&s_in[ci][2 * py + r][2 * px + 2];
            p[ci][r][0] = a.x;  p[ci][r][1] = a.y;
            p[ci][r][2] = c2.x; p[ci][r][3] = c2.y;
        }

    const int oy = blockIdx.y * 16 + py;
    const int ox = blockIdx.x * 16 + px;
    // padded store base: (oy+1, ox+1)
    float* hp = g_h + (size_t)b * C1_ * HP_CH + (oy + 1) * HP_C + (ox + 1);

#pragma unroll 2
    for (int oc = 0; oc < C1_; oc++) {
        float a00 = 0.f, a01 = 0.f, a10 = 0.f, a11 = 0.f;
        const float4* w4 = (const float4*)&s_w[oc * 36];
#pragma unroll
        for (int ci = 0; ci < 3; ci++)
#pragma unroll
            for (int ky = 0; ky < 3; ky++) {
                float4 w = w4[ci * 3 + ky];
                a00 = fmaf(p[ci][ky    ][0], w.x, a00);
                a01 = fmaf(p[ci][ky    ][1], w.x, a01);
                a10 = fmaf(p[ci][ky + 1][0], w.x, a10);
                a11 = fmaf(p[ci][ky + 1][1], w.x, a11);
                a00 = fmaf(p[ci][ky    ][1], w.y, a00);
                a01 = fmaf(p[ci][ky    ][2], w.y, a01);
                a10 = fmaf(p[ci][ky + 1][1], w.y, a10);
                a11 = fmaf(p[ci][ky + 1][2], w.y, a11);
                a00 = fmaf(p[ci][ky    ][2], w.z, a00);
                a01 = fmaf(p[ci][ky    ][3], w.z, a01);
                a10 = fmaf(p[ci][ky + 1][2], w.z, a10);
                a11 = fmaf(p[ci][ky + 1][3], w.z, a11);
            }
        float mv = fmaxf(fmaxf(a00, a01), fmaxf(a10, a11)) + s_bias[oc];
        hp[oc * HP_CH] = fmaxf(mv, 0.f);
    }
}

// ---------------------------------------------------------------------------
// Kernel 2: Conv(32->64, k3, s2, p1) + BN + Sigmoid + MaxPool2
// Grid (2,2,512), 256 thr. Static smem; padded-gmem fill: no bounds checks,
// vectorized LDG.128/STS.128 halo loads.
// ---------------------------------------------------------------------------
__global__ void __launch_bounds__(256) conv2_fused(
    const float* __restrict__ w2, const float* __restrict__ b2,
    const float* __restrict__ g2, const float* __restrict__ be2,
    const float* __restrict__ m2, const float* __restrict__ v2,
    float* __restrict__ feat)
{
    __shared__ __align__(16) float s_in[4][33][36];   // smem col j <-> padded col 32bx+j
    __shared__ __align__(16) float s_w[C2_ * 48];     // [oc][cil][ky][4] pre-scaled
    __shared__ float s_scale[C2_], s_bias[C2_];

    const int b  = blockIdx.z;
    const int bx = blockIdx.x, by = blockIdx.y;
    const int t  = threadIdx.x;

    if (t < C2_) {
        float inv = g2[t] * rsqrtf(v2[t] + 1e-5f);
        s_scale[t] = inv;
        s_bias[t]  = be2[t] + (b2[t] - m2[t]) * inv;
    }

    const int pix = t & 63, grp = t >> 6;          // grp 0..3 -> 16 oc each
    const int px = pix & 7, py = pix >> 3;

    float acc[16][2][2];
#pragma unroll
    for (int i = 0; i < 16; i++) {
        acc[i][0][0] = 0.f; acc[i][0][1] = 0.f;
        acc[i][1][0] = 0.f; acc[i][1][1] = 0.f;
    }

    // padded base for this tile: rows 32by.., cols 32bx..  (already include border shift)
    const float* hp = g_h + (size_t)b * C1_ * HP_CH + (32 * by) * HP_C + (32 * bx);

    for (int cc = 0; cc < 8; cc++) {               // 8 chunks of 4 input channels
        __syncthreads();
        // ---- weights chunk, pre-scaled + padded (scalar, tiny) ----
        for (int i = t; i < C2_ * 36; i += 256) {
            int oc = i / 36, rem = i % 36;
            int cil = rem / 9, k = rem % 9;
            int ky = k / 3, kx = k % 3;
            s_w[oc * 48 + cil * 12 + ky * 4 + kx] =
                w2[oc * (C1_ * 9) + (cc * 4 + cil) * 9 + k] * s_scale[oc];
        }
        // ---- input chunk: 4 ch x 33 rows, vectorized, no bounds checks ----
        // per (ch, r): 8x float4 (cols 0..31) + 1 float (col 32)
        for (int i = t; i < 4 * 33 * 9; i += 256) {
            int ch  = i / 297;
            int rem = i - ch * 297;
            int r   = rem / 9;
            int s   = rem - r * 9;
            const float* src = hp + (cc * 4 + ch) * HP_CH + r * HP_C;
            float* dst = &s_in[ch][r][0];
            if (s < 8) {
                *(float4*)(dst + 4 * s) = *(const float4*)(src + 4 * s);
            } else {
                dst[32] = src[32];
            }
        }
        __syncthreads();

#pragma unroll
        for (int cil = 0; cil < 4; cil++) {
            const float* row = &s_in[cil][4 * py][4 * px];
            float p[5][5];
#pragma unroll
            for (int r = 0; r < 5; r++) {
                float4 v4 = *(const float4*)(row + r * 36);
                p[r][0] = v4.x; p[r][1] = v4.y; p[r][2] = v4.z; p[r][3] = v4.w;
                p[r][4] = row[r * 36 + 4];
            }

#pragma unroll
            for (int oc = 0; oc < 16; oc++) {
                const float4* w4 = (const float4*)&s_w[(grp * 16 + oc) * 48 + cil * 12];
#pragma unroll
                for (int ky = 0; ky < 3; ky++) {
                    float4 w = w4[ky];
                    acc[oc][0][0] = fmaf(p[ky    ][0], w.x, acc[oc][0][0]);
                    acc[oc][0][1] = fmaf(p[ky    ][2], w.x, acc[oc][0][1]);
                    acc[oc][1][0] = fmaf(p[ky + 2][0], w.x, acc[oc][1][0]);
                    acc[oc][1][1] = fmaf(p[ky + 2][2], w.x, acc[oc][1][1]);
                    acc[oc][0][0] = fmaf(p[ky    ][1], w.y, acc[oc][0][0]);
                    acc[oc][0][1] = fmaf(p[ky    ][3], w.y, acc[oc][0][1]);
                    acc[oc][1][0] = fmaf(p[ky + 2][1], w.y, acc[oc][1][0]);
                    acc[oc][1][1] = fmaf(p[ky + 2][3], w.y, acc[oc][1][1]);
                    acc[oc][0][0] = fmaf(p[ky    ][2], w.z, acc[oc][0][0]);
                    acc[oc][0][1] = fmaf(p[ky    ][4], w.z, acc[oc][0][1]);
                    acc[oc][1][0] = fmaf(p[ky + 2][2], w.z, acc[oc][1][0]);
                    acc[oc][1][1] = fmaf(p[ky + 2][4], w.z, acc[oc][1][1]);
                }
            }
        }
    }

    // Epilogue: max-pool -> +bias -> sigmoid (conv pre-scaled; gamma>0)
    const int oy = by * 8 + py, ox = bx * 8 + px;
    float* fb = feat + (size_t)b * C2_ * 16 * 16;
#pragma unroll
    for (int oc = 0; oc < 16; oc++) {
        int c = grp * 16 + oc;
        float m = fmaxf(fmaxf(acc[oc][0][0], acc[oc][0][1]),
                        fmaxf(acc[oc][1][0], acc[oc][1][1]));
        float v = m + s_bias[c];
        fb[c * 256 + oy * 16 + ox] = 1.f / (1.f + __expf(-v));
    }
}

// ---------------------------------------------------------------------------
// Kernel 3: per-image mean over feat [64,16,16] -> scores + detected
// ---------------------------------------------------------------------------
__global__ void __launch_bounds__(256) score_reduce(
    const float* __restrict__ feat,
    float* __restrict__ scores,
    float* __restrict__ detected)
{
    const int b = blockIdx.x;
    const float4* fb = (const float4*)(feat + (size_t)b * 16384);
    float s = 0.f;
    for (int i = threadIdx.x; i < 4096; i += 256) {
        float4 v = fb[i];
        s += (v.x + v.y) + (v.z + v.w);
    }

    __shared__ float red[8];
#pragma unroll
    for (int o = 16; o > 0; o >>= 1) s += __shfl_down_sync(0xffffffffu, s, o);
    if ((threadIdx.x & 31) == 0) red[threadIdx.x >> 5] = s;
    __syncthreads();
    if (threadIdx.x < 8) {
        s = red[threadIdx.x];
#pragma unroll
        for (int o = 4; o > 0; o >>= 1) s += __shfl_down_sync(0xffu, s, o);
        if (threadIdx.x == 0) {
            float sc = s * (1.f / 16384.f);
            scores[b]   = sc;
            detected[b] = (sc >= 0.55f) ? 1.f : 0.f;
        }
    }
}

// ---------------------------------------------------------------------------
extern "C" void kernel_launch(void* const* d_in, const int* in_sizes, int n_in,
                              void* d_out, int out_size)
{
    const float* crops = (const float*)d_in[0];
    const float* w1  = (const float*)d_in[1];
    const float* b1  = (const float*)d_in[2];
    const float* g1  = (const float*)d_in[3];
    const float* be1 = (const float*)d_in[4];
    const float* m1  = (const float*)d_in[5];
    const float* v1  = (const float*)d_in[6];
    const float* w2  = (const float*)d_in[7];
    const float* b2  = (const float*)d_in[8];
    const float* g2  = (const float*)d_in[9];
    const float* be2 = (const float*)d_in[10];
    const float* m2  = (const float*)d_in[11];
    const float* v2  = (const float*)d_in[12];

    float* out      = (float*)d_out;
    float* feat     = out;                                   // 512*64*16*16
    float* scores   = out + (size_t)B_ * C2_ * 16 * 16;      // +512
    float* detected = scores + B_;                           // +512

    conv1_fused<<<dim3(4, 4, B_), 256>>>(crops, w1, b1, g1, be1, m1, v1);
    conv2_fused<<<dim3(2, 2, B_), 256>>>(w2, b2, g2, be2, m2, v2, feat);
    score_reduce<<<B_, 256>>>(feat, scores, detected);
}

// round 6
// speedup vs baseline: 1.6193x; 1.5098x over previous
#include <cuda_runtime.h>
#include <cstdint>

#define B_    512
#define HW_   128
#define C1_   32
#define C2_   64

// Padded intermediate h: [512][32][66][68], zero border. Valid data [1..64][1..64].
// Static __device__ -> zero-initialized; border never written (deterministic).
#define HP_R   66
#define HP_C   68
#define HP_CH  (HP_R * HP_C)          // 4488
__device__ float g_h[(size_t)B_ * C1_ * HP_CH];   // ~294 MB

// Pre-packed conv2 weights: [cc][oc][cil][ky][4], pre-scaled by BN scale.
// Padding lane (kx=3) stays zero from static init.
__device__ float g_w2p[8 * 3072];

// ---- cp.async helpers -----------------------------------------------------
__device__ __forceinline__ uint32_t sptr(const void* p) {
    return (uint32_t)__cvta_generic_to_shared(p);
}
__device__ __forceinline__ void cpa16(uint32_t dst, const void* src) {
    asm volatile("cp.async.cg.shared.global [%0], [%1], 16;" :: "r"(dst), "l"(src));
}
__device__ __forceinline__ void cpa4(uint32_t dst, const void* src) {
    asm volatile("cp.async.ca.shared.global [%0], [%1], 4;" :: "r"(dst), "l"(src));
}
__device__ __forceinline__ void cpa_commit() {
    asm volatile("cp.async.commit_group;" ::: "memory");
}
template <int N>
__device__ __forceinline__ void cpa_wait() {
    asm volatile("cp.async.wait_group %0;" :: "n"(N) : "memory");
}

// ---------------------------------------------------------------------------
// Kernel 0: pre-pack conv2 weights (tiny; 18432 items)
// ---------------------------------------------------------------------------
__global__ void conv2_prep(const float* __restrict__ w2,
                           const float* __restrict__ g2,
                           const float* __restrict__ v2)
{
    int i = blockIdx.x * 256 + threadIdx.x;
    if (i >= 8 * C2_ * 36) return;
    int cc  = i / (C2_ * 36);
    int rem = i % (C2_ * 36);
    int oc  = rem / 36;
    int k2  = rem % 36;
    int cil = k2 / 9, k = k2 % 9;
    int ky = k / 3, kx = k % 3;
    float inv = g2[oc] * rsqrtf(v2[oc] + 1e-5f);
    g_w2p[cc * 3072 + oc * 48 + cil * 12 + ky * 4 + kx] =
        w2[oc * (C1_ * 9) + (cc * 4 + cil) * 9 + k] * inv;
}

// ---------------------------------------------------------------------------
// Kernel 1: Conv(3->32, k3, s1, p1) + BN + ReLU + MaxPool2  (near FFMA wall)
// ---------------------------------------------------------------------------
__global__ void __launch_bounds__(256) conv1_fused(
    const float* __restrict__ crops,
    const float* __restrict__ w1, const float* __restrict__ b1,
    const float* __restrict__ g1, const float* __restrict__ be1,
    const float* __restrict__ m1, const float* __restrict__ v1)
{
    __shared__ float s_in[3][34][36];
    __shared__ __align__(16) float s_w[C1_ * 36];  // [oc][ci][ky][4] pre-scaled
    __shared__ float s_scale[C1_], s_bias[C1_];

    const int b   = blockIdx.z;
    const int cx0 = blockIdx.x * 32;
    const int cy0 = blockIdx.y * 32;
    const int t   = threadIdx.x;

    if (t < C1_) {
        float inv = g1[t] * rsqrtf(v1[t] + 1e-5f);
        s_scale[t] = inv;
        s_bias[t]  = be1[t] + (b1[t] - m1[t]) * inv;
    }

    const float* cb = crops + (size_t)b * 3 * HW_ * HW_;
    for (int i = t; i < 3 * 34 * 34; i += 256) {
        int ci = i / (34 * 34);
        int rem = i % (34 * 34);
        int r = rem / 34, c = rem % 34;
        int gr = cy0 - 1 + r, gc = cx0 - 1 + c;
        float v = 0.f;
        if (gr >= 0 && gr < HW_ && gc >= 0 && gc < HW_)
            v = cb[ci * HW_ * HW_ + gr * HW_ + gc];
        s_in[ci][r][c] = v;
    }
    __syncthreads();

    for (int i = t; i < C1_ * 27; i += 256) {
        int oc = i / 27, k = i % 27;
        int ci = k / 9, ky = (k % 9) / 3, kx = k % 3;
        s_w[oc * 36 + ci * 12 + ky * 4 + kx] = w1[i] * s_scale[oc];
    }
    __syncthreads();

    const int px = t & 15, py = t >> 4;

    float p[3][4][4];
#pragma unroll
    for (int ci = 0; ci < 3; ci++)
#pragma unroll
        for (int r = 0; r < 4; r++) {
            float2 a  = *(const float2*)&s_in[ci][2 * py + r][2 * px];
            float2 c2 = *(const float2*)&s_in[ci][2 * py + r][2 * px + 2];
            p[ci][r][0] = a.x;  p[ci][r][1] = a.y;
            p[ci][r][2] = c2.x; p[ci][r][3] = c2.y;
        }

    const int oy = blockIdx.y * 16 + py;
    const int ox = blockIdx.x * 16 + px;
    float* hp = g_h + (size_t)b * C1_ * HP_CH + (oy + 1) * HP_C + (ox + 1);

    for (int oc = 0; oc < C1_; oc++) {
        float a00 = 0.f, a01 = 0.f, a10 = 0.f, a11 = 0.f;
        const float4* w4 = (const float4*)&s_w[oc * 36];
#pragma unroll
        for (int ci = 0; ci < 3; ci++)
#pragma unroll
            for (int ky = 0; ky < 3; ky++) {
                float4 w = w4[ci * 3 + ky];
                a00 = fmaf(p[ci][ky    ][0], w.x, a00);
                a01 = fmaf(p[ci][ky    ][1], w.x, a01);
                a10 = fmaf(p[ci][ky + 1][0], w.x, a10);
                a11 = fmaf(p[ci][ky + 1][1], w.x, a11);
                a00 = fmaf(p[ci][ky    ][1], w.y, a00);
                a01 = fmaf(p[ci][ky    ][2], w.y, a01);
                a10 = fmaf(p[ci][ky + 1][1], w.y, a10);
                a11 = fmaf(p[ci][ky + 1][2], w.y, a11);
                a00 = fmaf(p[ci][ky    ][2], w.z, a00);
                a01 = fmaf(p[ci][ky    ][3], w.z, a01);
                a10 = fmaf(p[ci][ky + 1][2], w.z, a10);
                a11 = fmaf(p[ci][ky + 1][3], w.z, a11);
            }
        float mv = fmaxf(fmaxf(a00, a01), fmaxf(a10, a11)) + s_bias[oc];
        hp[oc * HP_CH] = fmaxf(mv, 0.f);
    }
}

// ---------------------------------------------------------------------------
// Kernel 2: Conv(32->64, k3, s2, p1) + BN + Sigmoid + MaxPool2
// 2-stage cp.async pipeline. Dynamic smem:
//   stage p (p=0,1) at float offset p*7824:
//     in : [4][33][36]   (4752 floats)
//     w  : [64][4][3][4] (3072 floats, offset 4752)
//   bias at 15648 (64 floats)
// ---------------------------------------------------------------------------
#define STG_F        7824
#define STG_W_OFF    4752
#define BI_OFF       15648
#define CONV2_SMEM_BYTES  ((2 * STG_F + 64) * 4)

__global__ void __launch_bounds__(256) conv2_fused(
    const float* __restrict__ b2, const float* __restrict__ g2,
    const float* __restrict__ be2, const float* __restrict__ m2,
    const float* __restrict__ v2,
    float* __restrict__ feat)
{
    extern __shared__ __align__(16) float sm[];

    const int b  = blockIdx.z;
    const int bx = blockIdx.x, by = blockIdx.y;
    const int t  = threadIdx.x;

    if (t < C2_) {
        float inv = g2[t] * rsqrtf(v2[t] + 1e-5f);
        sm[BI_OFF + t] = be2[t] + (b2[t] - m2[t]) * inv;
    }

    const float* hp = g_h + (size_t)b * C1_ * HP_CH + (32 * by) * HP_C + (32 * bx);
    const uint32_t sm_u32 = sptr(sm);

    // ---- issue async copies for chunk cc into stage p (no waiting) ----
    auto issue = [&](int cc, int p) {
        const uint32_t base = sm_u32 + (uint32_t)(p * STG_F) * 4u;
        // inputs: 4 ch x 33 rows x (8 float4 + 1 float)
        for (int i = t; i < 4 * 33 * 9; i += 256) {
            int ch  = i / 297;
            int rem = i - ch * 297;
            int r   = rem / 9;
            int s   = rem - r * 9;
            const float* src = hp + (cc * 4 + ch) * HP_CH + r * HP_C;
            uint32_t dst = base + (uint32_t)((ch * 33 + r) * 36) * 4u;
            if (s < 8) cpa16(dst + 16u * s, src + 4 * s);
            else       cpa4(dst + 128u, src + 32);
        }
        // weights: 3072 floats = 768 x 16B, contiguous pre-packed
        const float4* ws = (const float4*)(g_w2p + cc * 3072);
        const uint32_t wb = base + STG_W_OFF * 4u;
        for (int i = t; i < 768; i += 256)
            cpa16(wb + 16u * i, ws + i);
        cpa_commit();
    };

    const int pix = t & 63, grp = t >> 6;      // grp 0..3 -> 16 oc each
    const int px = pix & 7, py = pix >> 3;

    float acc[16][2][2];
#pragma unroll
    for (int i = 0; i < 16; i++) {
        acc[i][0][0] = 0.f; acc[i][0][1] = 0.f;
        acc[i][1][0] = 0.f; acc[i][1][1] = 0.f;
    }

    issue(0, 0);

    for (int cc = 0; cc < 8; cc++) {
        const int cur = cc & 1;
        if (cc < 7) { issue(cc + 1, cur ^ 1); cpa_wait<1>(); }
        else        { cpa_wait<0>(); }
        __syncthreads();                       // stage cur visible to all

        const float* sin = sm + cur * STG_F;
        const float* sw  = sin + STG_W_OFF;

#pragma unroll
        for (int cil = 0; cil < 4; cil++) {
            const float* row = sin + (cil * 33 + 4 * py) * 36 + 4 * px;
            float p[5][5];
#pragma unroll
            for (int r = 0; r < 5; r++) {
                float4 v4 = *(const float4*)(row + r * 36);
                p[r][0] = v4.x; p[r][1] = v4.y; p[r][2] = v4.z; p[r][3] = v4.w;
                p[r][4] = row[r * 36 + 4];
            }

#pragma unroll
            for (int oc = 0; oc < 16; oc++) {
                const float4* w4 = (const float4*)(sw + (grp * 16 + oc) * 48 + cil * 12);
#pragma unroll
                for (int ky = 0; ky < 3; ky++) {
                    float4 w = w4[ky];
                    acc[oc][0][0] = fmaf(p[ky    ][0], w.x, acc[oc][0][0]);
                    acc[oc][0][1] = fmaf(p[ky    ][2], w.x, acc[oc][0][1]);
                    acc[oc][1][0] = fmaf(p[ky + 2][0], w.x, acc[oc][1][0]);
                    acc[oc][1][1] = fmaf(p[ky + 2][2], w.x, acc[oc][1][1]);
                    acc[oc][0][0] = fmaf(p[ky    ][1], w.y, acc[oc][0][0]);
                    acc[oc][0][1] = fmaf(p[ky    ][3], w.y, acc[oc][0][1]);
                    acc[oc][1][0] = fmaf(p[ky + 2][1], w.y, acc[oc][1][0]);
                    acc[oc][1][1] = fmaf(p[ky + 2][3], w.y, acc[oc][1][1]);
                    acc[oc][0][0] = fmaf(p[ky    ][2], w.z, acc[oc][0][0]);
                    acc[oc][0][1] = fmaf(p[ky    ][4], w.z, acc[oc][0][1]);
                    acc[oc][1][0] = fmaf(p[ky + 2][2], w.z, acc[oc][1][0]);
                    acc[oc][1][1] = fmaf(p[ky + 2][4], w.z, acc[oc][1][1]);
                }
            }
        }
        __syncthreads();   // all readers of stage cur done before it is refilled
    }

    // Epilogue: max-pool -> +bias -> sigmoid (conv pre-scaled; gamma>0)
    const int oy = by * 8 + py, ox = bx * 8 + px;
    float* fb = feat + (size_t)b * C2_ * 16 * 16;
#pragma unroll
    for (int oc = 0; oc < 16; oc++) {
        int c = grp * 16 + oc;
        float m = fmaxf(fmaxf(acc[oc][0][0], acc[oc][0][1]),
                        fmaxf(acc[oc][1][0], acc[oc][1][1]));
        float v = m + sm[BI_OFF + c];
        fb[c * 256 + oy * 16 + ox] = 1.f / (1.f + __expf(-v));
    }
}

// ---------------------------------------------------------------------------
// Kernel 3: per-image mean over feat [64,16,16] -> scores + detected
// ---------------------------------------------------------------------------
__global__ void __launch_bounds__(256) score_reduce(
    const float* __restrict__ feat,
    float* __restrict__ scores,
    float* __restrict__ detected)
{
    const int b = blockIdx.x;
    const float4* fb = (const float4*)(feat + (size_t)b * 16384);
    float s = 0.f;
    for (int i = threadIdx.x; i < 4096; i += 256) {
        float4 v = fb[i];
        s += (v.x + v.y) + (v.z + v.w);
    }

    __shared__ float red[8];
#pragma unroll
    for (int o = 16; o > 0; o >>= 1) s += __shfl_down_sync(0xffffffffu, s, o);
    if ((threadIdx.x & 31) == 0) red[threadIdx.x >> 5] = s;
    __syncthreads();
    if (threadIdx.x < 8) {
        s = red[threadIdx.x];
#pragma unroll
        for (int o = 4; o > 0; o >>= 1) s += __shfl_down_sync(0xffu, s, o);
        if (threadIdx.x == 0) {
            float sc = s * (1.f / 16384.f);
            scores[b]   = sc;
            detected[b] = (sc >= 0.55f) ? 1.f : 0.f;
        }
    }
}

// ---------------------------------------------------------------------------
extern "C" void kernel_launch(void* const* d_in, const int* in_sizes, int n_in,
                              void* d_out, int out_size)
{
    const float* crops = (const float*)d_in[0];
    const float* w1  = (const float*)d_in[1];
    const float* b1  = (const float*)d_in[2];
    const float* g1  = (const float*)d_in[3];
    const float* be1 = (const float*)d_in[4];
    const float* m1  = (const float*)d_in[5];
    const float* v1  = (const float*)d_in[6];
    const float* w2  = (const float*)d_in[7];
    const float* b2  = (const float*)d_in[8];
    const float* g2  = (const float*)d_in[9];
    const float* be2 = (const float*)d_in[10];
    const float* m2  = (const float*)d_in[11];
    const float* v2  = (const float*)d_in[12];

    float* out      = (float*)d_out;
    float* feat     = out;                                   // 512*64*16*16
    float* scores   = out + (size_t)B_ * C2_ * 16 * 16;      // +512
    float* detected = scores + B_;                           // +512

    static int smem_set = 0;
    if (!smem_set) {
        cudaFuncSetAttribute(conv2_fused,
                             cudaFuncAttributeMaxDynamicSharedMemorySize,
                             CONV2_SMEM_BYTES);
        smem_set = 1;
    }

    conv2_prep<<<72, 256>>>(w2, g2, v2);
    conv1_fused<<<dim3(4, 4, B_), 256>>>(crops, w1, b1, g1, be1, m1, v1);
    conv2_fused<<<dim3(2, 2, B_), 256, CONV2_SMEM_BYTES>>>(b2, g2, be2, m2, v2, feat);
    score_reduce<<<B_, 256>>>(feat, scores, detected);
}